// round 1
// baseline (speedup 1.0000x reference)
#include <cuda_runtime.h>
#include <cuda_bf16.h>
#include <cstddef>

// Problem constants
#define BB 8
#define SS 1024
#define EE 1024
#define HH 16
#define DD 64
// tokens total
#define MTOT (BB*SS)          // 8192
#define HEADS (BB*HH)         // 128
#define HEAD_ELEMS (SS*DD)    // 65536

// Scratch (allocation-free rule: __device__ globals)
__device__ float g_q[MTOT*EE];
__device__ float g_k[MTOT*EE];
__device__ float g_v[MTOT*EE];
__device__ float g_ctx[MTOT*EE];
__device__ float g_sc[(size_t)HEADS*SS*SS];   // 128*1024*1024 = 512MB

// ---------------------------------------------------------------------------
// SGEMM: C[M,N] = A[M,K] @ B[K,N] (+ bias). 128x128 tile, BK=16, 256 thr, 8x8/thr
// Requires M%128==0, N%128==0, K%16==0 (true for all uses here).
// ---------------------------------------------------------------------------
__global__ __launch_bounds__(256, 2)
void sgemm_bias(const float* __restrict__ A, const float* __restrict__ B,
                float* __restrict__ C, const float* __restrict__ bias,
                int M, int N, int K)
{
    __shared__ float As[16][128];   // transposed: As[k][m]
    __shared__ float Bs[16][128];   // natural:    Bs[k][n]

    const int tid = threadIdx.x;
    const int tx  = tid & 15;       // 0..15 -> 8 cols each
    const int ty  = tid >> 4;       // 0..15 -> 8 rows each
    const int bx  = blockIdx.x;     // N tile
    const int by  = blockIdx.y;     // M tile

    const float* Ablk = A + (size_t)by * 128 * K;
    const float* Bblk = B + (size_t)bx * 128;

    float acc[8][8];
    #pragma unroll
    for (int i = 0; i < 8; i++)
        #pragma unroll
        for (int j = 0; j < 8; j++) acc[i][j] = 0.f;

    for (int k0 = 0; k0 < K; k0 += 16) {
        // Load A tile 128x16 (512 float4), transpose into As
        #pragma unroll
        for (int i = 0; i < 2; i++) {
            int idx = tid + i * 256;          // 0..511
            int r   = idx >> 2;               // 0..127
            int c4  = idx & 3;                // 0..3
            float4 v = *(const float4*)(Ablk + (size_t)r * K + k0 + c4 * 4);
            As[c4*4+0][r] = v.x; As[c4*4+1][r] = v.y;
            As[c4*4+2][r] = v.z; As[c4*4+3][r] = v.w;
        }
        // Load B tile 16x128 (512 float4)
        #pragma unroll
        for (int i = 0; i < 2; i++) {
            int idx = tid + i * 256;
            int r   = idx >> 5;               // 0..15
            int c4  = idx & 31;               // 0..31
            float4 v = *(const float4*)(Bblk + (size_t)(k0 + r) * N + c4 * 4);
            *(float4*)&Bs[r][c4 * 4] = v;
        }
        __syncthreads();

        #pragma unroll
        for (int k = 0; k < 16; k++) {
            float a[8], b[8];
            #pragma unroll
            for (int i = 0; i < 8; i++) a[i] = As[k][ty * 8 + i];
            #pragma unroll
            for (int j = 0; j < 8; j++) b[j] = Bs[k][tx * 8 + j];
            #pragma unroll
            for (int i = 0; i < 8; i++)
                #pragma unroll
                for (int j = 0; j < 8; j++) acc[i][j] += a[i] * b[j];
        }
        __syncthreads();
    }

    float* Cblk = C + (size_t)by * 128 * N + (size_t)bx * 128;
    #pragma unroll
    for (int i = 0; i < 8; i++) {
        int r = ty * 8 + i;
        #pragma unroll
        for (int j = 0; j < 8; j += 4) {
            int c = tx * 8 + j;
            float4 bv = make_float4(0.f, 0.f, 0.f, 0.f);
            if (bias) bv = *(const float4*)(bias + bx * 128 + c);
            float4 v;
            v.x = acc[i][j+0] + bv.x;
            v.y = acc[i][j+1] + bv.y;
            v.z = acc[i][j+2] + bv.z;
            v.w = acc[i][j+3] + bv.w;
            *(float4*)(Cblk + (size_t)r * N + c) = v;
        }
    }
}

// ---------------------------------------------------------------------------
// Scores: Sc[z,i,j] = (1/32) * dot(Q[z,i,:], K[z,j,:])   (D=64)
// 128x128 output tile per block, BK=32 (two iters over D), 256 thr, 8x8/thr
// ---------------------------------------------------------------------------
__global__ __launch_bounds__(256, 2)
void scores_kernel(const float* __restrict__ Q, const float* __restrict__ K,
                   float* __restrict__ Sc)
{
    __shared__ float Qs[32][128];   // Qs[d][i]
    __shared__ float Ks[32][128];   // Ks[d][j]

    const int z = blockIdx.z;
    const float* Qh = Q + (size_t)z * HEAD_ELEMS;
    const float* Kh = K + (size_t)z * HEAD_ELEMS;
    float* Sh = Sc + (size_t)z * SS * SS;

    const int tid = threadIdx.x;
    const int tx  = tid & 15;
    const int ty  = tid >> 4;
    const int rowbase = blockIdx.y * 128;
    const int colbase = blockIdx.x * 128;

    float acc[8][8];
    #pragma unroll
    for (int i = 0; i < 8; i++)
        #pragma unroll
        for (int j = 0; j < 8; j++) acc[i][j] = 0.f;

    for (int d0 = 0; d0 < DD; d0 += 32) {
        // 128 rows x 32 dims per operand = 1024 float4; 4 per thread each
        #pragma unroll
        for (int i = 0; i < 4; i++) {
            int idx = tid + i * 256;          // 0..1023
            int r   = idx >> 3;               // 0..127
            int c4  = idx & 7;                // 0..7
            float4 v = *(const float4*)(Qh + (size_t)(rowbase + r) * DD + d0 + c4 * 4);
            Qs[c4*4+0][r] = v.x; Qs[c4*4+1][r] = v.y;
            Qs[c4*4+2][r] = v.z; Qs[c4*4+3][r] = v.w;
            float4 w = *(const float4*)(Kh + (size_t)(colbase + r) * DD + d0 + c4 * 4);
            Ks[c4*4+0][r] = w.x; Ks[c4*4+1][r] = w.y;
            Ks[c4*4+2][r] = w.z; Ks[c4*4+3][r] = w.w;
        }
        __syncthreads();

        #pragma unroll
        for (int d = 0; d < 32; d++) {
            float a[8], b[8];
            #pragma unroll
            for (int i = 0; i < 8; i++) a[i] = Qs[d][ty * 8 + i];
            #pragma unroll
            for (int j = 0; j < 8; j++) b[j] = Ks[d][tx * 8 + j];
            #pragma unroll
            for (int i = 0; i < 8; i++)
                #pragma unroll
                for (int j = 0; j < 8; j++) acc[i][j] += a[i] * b[j];
        }
        __syncthreads();
    }

    const float scale = 0.03125f;  // E^-0.5 = 1/32 (reference quirk)
    #pragma unroll
    for (int i = 0; i < 8; i++) {
        int r = rowbase + ty * 8 + i;
        #pragma unroll
        for (int j = 0; j < 8; j += 4) {
            int c = colbase + tx * 8 + j;
            float4 v;
            v.x = acc[i][j+0] * scale;
            v.y = acc[i][j+1] * scale;
            v.z = acc[i][j+2] * scale;
            v.w = acc[i][j+3] * scale;
            *(float4*)(Sh + (size_t)r * SS + c) = v;
        }
    }
}

// ---------------------------------------------------------------------------
// Softmax over last axis: one block (128 thr) per row of 1024
// ---------------------------------------------------------------------------
__global__ __launch_bounds__(128)
void softmax_kernel(float* __restrict__ Sc)
{
    float4* p = (float4*)(Sc + (size_t)blockIdx.x * SS);
    const int tid  = threadIdx.x;
    const int lane = tid & 31;
    const int wid  = tid >> 5;

    float4 a = p[tid];
    float4 b = p[tid + 128];

    float m = fmaxf(fmaxf(fmaxf(a.x, a.y), fmaxf(a.z, a.w)),
                    fmaxf(fmaxf(b.x, b.y), fmaxf(b.z, b.w)));
    #pragma unroll
    for (int o = 16; o; o >>= 1) m = fmaxf(m, __shfl_xor_sync(0xffffffffu, m, o));

    __shared__ float sm[4];
    __shared__ float ssum[4];
    if (lane == 0) sm[wid] = m;
    __syncthreads();
    m = fmaxf(fmaxf(sm[0], sm[1]), fmaxf(sm[2], sm[3]));

    a.x = __expf(a.x - m); a.y = __expf(a.y - m);
    a.z = __expf(a.z - m); a.w = __expf(a.w - m);
    b.x = __expf(b.x - m); b.y = __expf(b.y - m);
    b.z = __expf(b.z - m); b.w = __expf(b.w - m);

    float s = a.x + a.y + a.z + a.w + b.x + b.y + b.z + b.w;
    #pragma unroll
    for (int o = 16; o; o >>= 1) s += __shfl_xor_sync(0xffffffffu, s, o);
    if (lane == 0) ssum[wid] = s;
    __syncthreads();
    s = ssum[0] + ssum[1] + ssum[2] + ssum[3];

    float inv = 1.0f / s;
    a.x *= inv; a.y *= inv; a.z *= inv; a.w *= inv;
    b.x *= inv; b.y *= inv; b.z *= inv; b.w *= inv;
    p[tid] = a;
    p[tid + 128] = b;
}

// ---------------------------------------------------------------------------
// PV: for head z: O[1024,64] = P[1024,1024] @ V[1024,64],
// scattered into ctx[b, s, h*64+d].  BM=128, BN=64, BK=16, 256 thr, 8x4/thr
// ---------------------------------------------------------------------------
__global__ __launch_bounds__(256)
void pv_kernel(const float* __restrict__ Sc, const float* __restrict__ V,
               float* __restrict__ ctx)
{
    __shared__ float Ps[16][128];   // Ps[k][i]
    __shared__ float Vs[16][64];    // Vs[k][j]

    const int z = blockIdx.z;
    const int b = z >> 4;           // z / 16
    const int h = z & 15;
    const float* Ph = Sc + (size_t)z * SS * SS;
    const float* Vh = V  + (size_t)z * HEAD_ELEMS;

    const int tid = threadIdx.x;
    const int tx  = tid & 15;       // 16 groups of 4 cols
    const int ty  = tid >> 4;       // 16 groups of 8 rows
    const int rowbase = blockIdx.x * 128;

    float acc[8][4];
    #pragma unroll
    for (int i = 0; i < 8; i++)
        #pragma unroll
        for (int j = 0; j < 4; j++) acc[i][j] = 0.f;

    for (int k0 = 0; k0 < SS; k0 += 16) {
        // P tile 128x16 = 512 float4, transposed
        #pragma unroll
        for (int i = 0; i < 2; i++) {
            int idx = tid + i * 256;
            int r   = idx >> 2;
            int c4  = idx & 3;
            float4 v = *(const float4*)(Ph + (size_t)(rowbase + r) * SS + k0 + c4 * 4);
            Ps[c4*4+0][r] = v.x; Ps[c4*4+1][r] = v.y;
            Ps[c4*4+2][r] = v.z; Ps[c4*4+3][r] = v.w;
        }
        // V tile 16x64 = 256 float4, natural
        {
            int r  = tid >> 4;      // 0..15
            int c4 = tid & 15;      // 0..15
            float4 v = *(const float4*)(Vh + (size_t)(k0 + r) * DD + c4 * 4);
            *(float4*)&Vs[r][c4 * 4] = v;
        }
        __syncthreads();

        #pragma unroll
        for (int k = 0; k < 16; k++) {
            float a[8], bb[4];
            #pragma unroll
            for (int i = 0; i < 8; i++) a[i] = Ps[k][ty * 8 + i];
            #pragma unroll
            for (int j = 0; j < 4; j++) bb[j] = Vs[k][tx * 4 + j];
            #pragma unroll
            for (int i = 0; i < 8; i++)
                #pragma unroll
                for (int j = 0; j < 4; j++) acc[i][j] += a[i] * bb[j];
        }
        __syncthreads();
    }

    // ctx[b, s, h*64 + d]
    #pragma unroll
    for (int i = 0; i < 8; i++) {
        int srow = rowbase + ty * 8 + i;
        float4 v;
        v.x = acc[i][0]; v.y = acc[i][1]; v.z = acc[i][2]; v.w = acc[i][3];
        *(float4*)(ctx + ((size_t)b * SS + srow) * EE + h * DD + tx * 4) = v;
    }
}

// ---------------------------------------------------------------------------
// Launch
// ---------------------------------------------------------------------------
extern "C" void kernel_launch(void* const* d_in, const int* in_sizes, int n_in,
                              void* d_out, int out_size)
{
    const float* hs = (const float*)d_in[0];
    const float* wq = (const float*)d_in[1];
    const float* wk = (const float*)d_in[2];
    const float* wv = (const float*)d_in[3];
    const float* wo = (const float*)d_in[4];
    const float* bo = (const float*)d_in[5];
    float* out = (float*)d_out;

    float *q, *k, *v, *ctx, *sc;
    cudaGetSymbolAddress((void**)&q,   g_q);
    cudaGetSymbolAddress((void**)&k,   g_k);
    cudaGetSymbolAddress((void**)&v,   g_v);
    cudaGetSymbolAddress((void**)&ctx, g_ctx);
    cudaGetSymbolAddress((void**)&sc,  g_sc);

    dim3 gProj(EE / 128, MTOT / 128);            // (8, 64)
    sgemm_bias<<<gProj, 256>>>(hs, wq, q, nullptr, MTOT, EE, EE);
    sgemm_bias<<<gProj, 256>>>(hs, wk, k, nullptr, MTOT, EE, EE);
    sgemm_bias<<<gProj, 256>>>(hs, wv, v, nullptr, MTOT, EE, EE);

    dim3 gSc(SS / 128, SS / 128, HEADS);         // (8, 8, 128)
    scores_kernel<<<gSc, 256>>>(q, k, sc);

    softmax_kernel<<<HEADS * SS, 128>>>(sc);     // 131072 rows

    dim3 gPV(SS / 128, 1, HEADS);                // (8, 1, 128)
    pv_kernel<<<gPV, 256>>>(sc, v, ctx);

    sgemm_bias<<<gProj, 256>>>(ctx, wo, out, bo, MTOT, EE, EE);
}

// round 4
// speedup vs baseline: 1.1068x; 1.1068x over previous
#include <cuda_runtime.h>
#include <cstdint>
#include <cstddef>

// Problem constants
#define BBATCH 8
#define SSEQ 1024
#define EEMB 1024
#define NHEAD 16
#define DHEAD 64
#define MTOT (BBATCH*SSEQ)          // 8192
#define HEADS (BBATCH*NHEAD)        // 128
#define HEAD_ELEMS (SSEQ*DHEAD)     // 65536

// Scratch (__device__ globals; allocation-free rule)
__device__ float g_q[(size_t)MTOT*EEMB];
__device__ float g_k[(size_t)MTOT*EEMB];
__device__ float g_v[(size_t)MTOT*EEMB];
__device__ float g_ctx[(size_t)MTOT*EEMB];
__device__ float g_sc[(size_t)HEADS*SSEQ*SSEQ];   // 512MB

// ---------------------------------------------------------------------------
// Helpers (baseline ISA only — no tcgen05 on this toolchain target)
// ---------------------------------------------------------------------------
__device__ __forceinline__ uint32_t f2tf32(float f){
    uint32_t u; asm("cvt.rna.tf32.f32 %0, %1;" : "=r"(u) : "f"(f)); return u;
}
__device__ __forceinline__ void mma_tf32(float* d, const uint32_t* a, const uint32_t* b){
    asm volatile("mma.sync.aligned.m16n8k8.row.col.f32.tf32.tf32.f32 "
        "{%0,%1,%2,%3}, {%4,%5,%6,%7}, {%8,%9}, {%0,%1,%2,%3};"
        : "+f"(d[0]), "+f"(d[1]), "+f"(d[2]), "+f"(d[3])
        : "r"(a[0]), "r"(a[1]), "r"(a[2]), "r"(a[3]), "r"(b[0]), "r"(b[1]));
}

// ---------------------------------------------------------------------------
// tf32 mma.sync GEMM: D[m,n] = alpha * sum_k A[m,k]*Bel(k,n) (+bias[n])
//   A: row-major [M,K] (row stride K)
//   B: BKN=true  -> stored [K,N] row-major (row stride ldB):  Bel(k,n)=B[k*ldB+n]
//      BKN=false -> stored [N,K] row-major (row stride K):    Bel(k,n)=B[n*K+k]
// Tile: 128 x BN, BK=32. 8 warps (2x4), warp tile 64 x (BN/4).
// SMEM holds operands pre-converted to tf32 in m16n8k8 FRAGMENT ORDER:
//   A frag:  af[(mtile*4+kstep)*128 + lane*4]{4}  (mtile: 16 rows, kstep: 8 k)
//   B frag:  bf[(ntile*4+kstep)*64  + lane*2]{2}  (ntile: 8 cols)
// so compute reads are vectorized ld.shared.v4 / v2.
// CMODE 0: C + z*Cz + row*ldC + col
// CMODE 1: ctx scatter: C + (z/16)*S*E + row*E + (z%16)*64 + col
// ---------------------------------------------------------------------------
template<int BN, bool BKN, int CMODE>
__global__ __launch_bounds__(256, 1)
void gemm_mma(const float* __restrict__ A, const float* __restrict__ B,
              float* __restrict__ C, const float* __restrict__ bias,
              int K, int ldB, float alpha,
              size_t Az, size_t Bz, size_t Cz, int ldC)
{
    extern __shared__ uint32_t smem[];
    constexpr int NTW   = BN/32;          // n-tiles per warp
    constexpr int AFRAG = 128*32;         // uint32 per A buffer (4096)
    constexpr int BFRAG = BN*32;          // uint32 per B buffer
    constexpr int IT_B  = (32*BN)/1024;   // float4 load iters for B (4 or 2)
    constexpr int C4B   = BN/4;           // float4 per B row (KN mode)

    const int tid  = threadIdx.x;
    const int lane = tid & 31, wid = tid >> 5;
    const int wm = wid >> 2, wn = wid & 3;
    const int z = blockIdx.z;
    A += (size_t)z * Az;
    B += (size_t)z * Bz;
    const int rowbase = blockIdx.y * 128;
    const int colbase = blockIdx.x * BN;

    float acc[4][NTW][4];
    #pragma unroll
    for (int mi = 0; mi < 4; mi++)
        #pragma unroll
        for (int ni = 0; ni < NTW; ni++)
            #pragma unroll
            for (int j = 0; j < 4; j++) acc[mi][ni][j] = 0.f;

    const int NC = K >> 5;
    float4 fa[4], fb[IT_B];

    // ---- gmem chunk load (regs) ----
    auto load_chunk = [&](int k0) {
        #pragma unroll
        for (int i = 0; i < 4; i++) {
            int idx = tid + (i<<8); int r = idx>>3, c4 = idx&7;
            fa[i] = *(const float4*)(A + (size_t)(rowbase+r)*K + k0 + (c4<<2));
        }
        if (BKN) {
            #pragma unroll
            for (int i = 0; i < IT_B; i++) {
                int idx = tid + (i<<8); int kk = idx / C4B, c4 = idx % C4B;
                fb[i] = *(const float4*)(B + (size_t)(k0+kk)*ldB + colbase + (c4<<2));
            }
        } else {
            #pragma unroll
            for (int i = 0; i < IT_B; i++) {
                int idx = tid + (i<<8); int n = idx>>3, c4 = idx&7;
                fb[i] = *(const float4*)(B + (size_t)(colbase+n)*K + k0 + (c4<<2));
            }
        }
    };

    load_chunk(0);

    for (int c = 0; c < NC; c++) {
        uint32_t* af = smem + (c&1)*(AFRAG+BFRAG);
        uint32_t* bf = af + AFRAG;

        // ---- scatter-store regs -> fragment-ordered smem (with tf32 cvt) ----
        #pragma unroll
        for (int i = 0; i < 4; i++) {
            int idx = tid + (i<<8); int r = idx>>3, c4 = idx&7;
            int mtile = r>>4, rr = r&15;
            int kst = c4>>1;
            uint32_t base = (uint32_t)((mtile*4 + kst)*128)
                          + ((rr&7)<<4) + ((c4&1)<<1) + (rr>>3);
            const float* pv = &fa[i].x;
            #pragma unroll
            for (int j = 0; j < 4; j++)
                af[base + (j<<2)] = f2tf32(pv[j]);
        }
        if (BKN) {
            #pragma unroll
            for (int i = 0; i < IT_B; i++) {
                int idx = tid + (i<<8); int kk = idx / C4B, c4 = idx % C4B;
                int kst = kk>>3, kr = kk&7;
                int ntile = c4>>1;
                uint32_t base = (uint32_t)((ntile*4 + kst)*64)
                              + ((c4&1)<<5) + ((kr&3)<<1) + (kr>>2);
                const float* pv = &fb[i].x;
                #pragma unroll
                for (int j = 0; j < 4; j++)
                    bf[base + (j<<3)] = f2tf32(pv[j]);
            }
        } else {
            #pragma unroll
            for (int i = 0; i < IT_B; i++) {
                int idx = tid + (i<<8); int n = idx>>3, c4 = idx&7;
                int ntile = n>>3, g = n&7;
                int kst = c4>>1;
                uint32_t base = (uint32_t)((ntile*4 + kst)*64)
                              + (g<<3) + (c4&1);
                const float* pv = &fb[i].x;
                #pragma unroll
                for (int j = 0; j < 4; j++)
                    bf[base + (j<<1)] = f2tf32(pv[j]);
            }
        }

        // prefetch next chunk while the barrier + compute hide the latency
        if (c + 1 < NC) load_chunk((c+1) << 5);

        __syncthreads();

        // ---- compute: 4 k-steps of m16n8k8 ----
        #pragma unroll
        for (int ks = 0; ks < 4; ks++) {
            uint4 av[4]; uint2 bv[NTW];
            #pragma unroll
            for (int mi = 0; mi < 4; mi++) {
                int mtile = wm*4 + mi;
                av[mi] = *(const uint4*)(af + ((mtile*4 + ks)*32 + lane)*4);
            }
            #pragma unroll
            for (int ni = 0; ni < NTW; ni++) {
                int ntile = wn*NTW + ni;
                bv[ni] = *(const uint2*)(bf + ((ntile*4 + ks)*32 + lane)*2);
            }
            #pragma unroll
            for (int mi = 0; mi < 4; mi++)
                #pragma unroll
                for (int ni = 0; ni < NTW; ni++)
                    mma_tf32(acc[mi][ni], (const uint32_t*)&av[mi], (const uint32_t*)&bv[ni]);
        }
    }
    // NOTE: no trailing sync needed; epilogue reads only registers.

    // ---- epilogue: regs -> gmem ----
    const int g = lane >> 2, t = lane & 3;
    #pragma unroll
    for (int mi = 0; mi < 4; mi++) {
        int row = rowbase + (wm*4 + mi)*16 + g;
        #pragma unroll
        for (int ni = 0; ni < NTW; ni++) {
            int col = colbase + (wn*NTW + ni)*8 + 2*t;
            float2 b0 = make_float2(0.f, 0.f);
            if (CMODE == 0 && bias) b0 = *(const float2*)(bias + col);
            float2 v0, v1;
            v0.x = acc[mi][ni][0]*alpha + b0.x;
            v0.y = acc[mi][ni][1]*alpha + b0.y;
            v1.x = acc[mi][ni][2]*alpha + b0.x;
            v1.y = acc[mi][ni][3]*alpha + b0.y;
            if (CMODE == 0) {
                float* p = C + (size_t)z*Cz + (size_t)row*ldC + col;
                *(float2*)p            = v0;
                *(float2*)(p + 8*ldC)  = v1;
            } else {
                float* p = C + (size_t)(z>>4)*SSEQ*EEMB + (size_t)row*EEMB
                             + (z&15)*DHEAD + col;
                *(float2*)p              = v0;
                *(float2*)(p + 8*EEMB)   = v1;
            }
        }
    }
}

// ---------------------------------------------------------------------------
// Softmax over last axis (1024), one block (128 thr) per row
// ---------------------------------------------------------------------------
__global__ __launch_bounds__(128)
void softmax_kernel(float* __restrict__ Sc)
{
    float4* p = (float4*)(Sc + (size_t)blockIdx.x * SSEQ);
    const int tid  = threadIdx.x;
    const int lane = tid & 31;
    const int wid  = tid >> 5;

    float4 a = p[tid];
    float4 b = p[tid + 128];

    float m = fmaxf(fmaxf(fmaxf(a.x, a.y), fmaxf(a.z, a.w)),
                    fmaxf(fmaxf(b.x, b.y), fmaxf(b.z, b.w)));
    #pragma unroll
    for (int o = 16; o; o >>= 1) m = fmaxf(m, __shfl_xor_sync(0xffffffffu, m, o));

    __shared__ float sm[4];
    __shared__ float ssum[4];
    if (lane == 0) sm[wid] = m;
    __syncthreads();
    m = fmaxf(fmaxf(sm[0], sm[1]), fmaxf(sm[2], sm[3]));

    a.x = __expf(a.x - m); a.y = __expf(a.y - m);
    a.z = __expf(a.z - m); a.w = __expf(a.w - m);
    b.x = __expf(b.x - m); b.y = __expf(b.y - m);
    b.z = __expf(b.z - m); b.w = __expf(b.w - m);

    float s = a.x + a.y + a.z + a.w + b.x + b.y + b.z + b.w;
    #pragma unroll
    for (int o = 16; o; o >>= 1) s += __shfl_xor_sync(0xffffffffu, s, o);
    if (lane == 0) ssum[wid] = s;
    __syncthreads();
    s = ssum[0] + ssum[1] + ssum[2] + ssum[3];

    float inv = 1.0f / s;
    a.x *= inv; a.y *= inv; a.z *= inv; a.w *= inv;
    b.x *= inv; b.y *= inv; b.z *= inv; b.w *= inv;
    p[tid] = a;
    p[tid + 128] = b;
}

// ---------------------------------------------------------------------------
// Launch
// ---------------------------------------------------------------------------
extern "C" void kernel_launch(void* const* d_in, const int* in_sizes, int n_in,
                              void* d_out, int out_size)
{
    const float* hs = (const float*)d_in[0];
    const float* wq = (const float*)d_in[1];
    const float* wk = (const float*)d_in[2];
    const float* wv = (const float*)d_in[3];
    const float* wo = (const float*)d_in[4];
    const float* bo = (const float*)d_in[5];
    float* out = (float*)d_out;

    float *q, *k, *v, *ctx, *sc;
    cudaGetSymbolAddress((void**)&q,   g_q);
    cudaGetSymbolAddress((void**)&k,   g_k);
    cudaGetSymbolAddress((void**)&v,   g_v);
    cudaGetSymbolAddress((void**)&ctx, g_ctx);
    cudaGetSymbolAddress((void**)&sc,  g_sc);

    const int SM128 = 2*(128*32 + 128*32)*4;   // 65536
    const int SM64  = 2*(128*32 +  64*32)*4;   // 49152
    cudaFuncSetAttribute(gemm_mma<128,true ,0>, cudaFuncAttributeMaxDynamicSharedMemorySize, SM128);
    cudaFuncSetAttribute(gemm_mma<128,false,0>, cudaFuncAttributeMaxDynamicSharedMemorySize, SM128);
    cudaFuncSetAttribute(gemm_mma<64 ,true ,1>, cudaFuncAttributeMaxDynamicSharedMemorySize, SM64);

    // Q/K/V projections: [8192,1024] = hs @ w   (w is [in,out] = KN layout)
    dim3 gProj(EEMB/128, MTOT/128, 1);          // (8, 64, 1)
    gemm_mma<128,true,0><<<gProj, 256, SM128>>>(hs, wq, q, nullptr, EEMB, EEMB, 1.0f, 0, 0, 0, EEMB);
    gemm_mma<128,true,0><<<gProj, 256, SM128>>>(hs, wk, k, nullptr, EEMB, EEMB, 1.0f, 0, 0, 0, EEMB);
    gemm_mma<128,true,0><<<gProj, 256, SM128>>>(hs, wv, v, nullptr, EEMB, EEMB, 1.0f, 0, 0, 0, EEMB);

    // Scores: per head z, Sc = (1/32) Q @ K^T  (K-matrix is [N=t, K=d] = NK layout)
    dim3 gSc(SSEQ/128, SSEQ/128, HEADS);        // (8, 8, 128)
    gemm_mma<128,false,0><<<gSc, 256, SM128>>>(q, k, sc, nullptr, DHEAD, 0, 0.03125f,
                                               (size_t)HEAD_ELEMS, (size_t)HEAD_ELEMS,
                                               (size_t)SSEQ*SSEQ, SSEQ);

    softmax_kernel<<<HEADS*SSEQ, 128>>>(sc);

    // PV: per head, O[1024,64] = P @ V  (V is [t, d] = KN layout), scatter into ctx
    dim3 gPV(1, SSEQ/128, HEADS);               // (1, 8, 128)
    gemm_mma<64,true,1><<<gPV, 256, SM64>>>(sc, v, ctx, nullptr, SSEQ, DHEAD, 1.0f,
                                            (size_t)SSEQ*SSEQ, (size_t)HEAD_ELEMS, 0, 0);

    // Output projection + bias (w_out is KN layout)
    gemm_mma<128,true,0><<<gProj, 256, SM128>>>(ctx, wo, out, bo, EEMB, EEMB, 1.0f, 0, 0, 0, EEMB);
}

// round 17
// speedup vs baseline: 1.2759x; 1.1528x over previous
#include <cuda_runtime.h>
#include <cstdint>
#include <cstddef>

// Problem constants
#define BBATCH 8
#define SSEQ 1024
#define EEMB 1024
#define NHEAD 16
#define DHEAD 64
#define MTOT (BBATCH*SSEQ)          // 8192
#define HEADS (BBATCH*NHEAD)        // 128
#define HEAD_ELEMS (SSEQ*DHEAD)     // 65536

// Scratch (__device__ globals; allocation-free rule)
__device__ float g_q[(size_t)MTOT*EEMB];
__device__ float g_k[(size_t)MTOT*EEMB];
__device__ float g_v[(size_t)MTOT*EEMB];
__device__ float g_ctx[(size_t)MTOT*EEMB];

// ---------------------------------------------------------------------------
// Helpers
// ---------------------------------------------------------------------------
__device__ __forceinline__ uint32_t f2tf32(float f){
    uint32_t u; asm("cvt.rna.tf32.f32 %0, %1;" : "=r"(u) : "f"(f)); return u;
}
__device__ __forceinline__ void mma_tf32(float* d, const uint32_t* a, const uint32_t* b){
    asm volatile("mma.sync.aligned.m16n8k8.row.col.f32.tf32.tf32.f32 "
        "{%0,%1,%2,%3}, {%4,%5,%6,%7}, {%8,%9}, {%0,%1,%2,%3};"
        : "+f"(d[0]), "+f"(d[1]), "+f"(d[2]), "+f"(d[3])
        : "r"(a[0]), "r"(a[1]), "r"(a[2]), "r"(a[3]), "r"(b[0]), "r"(b[1]));
}

// ---------------------------------------------------------------------------
// tf32 mma.sync GEMM (dense projections): D[m,n] = sum_k A[m,k]*B[k,n] (+bias)
// A row-major [M,K]; B stored [K,N] (row stride ldB). Tile 128x128, BK=32.
// 8 warps (2x4), warp tile 64x32. SMEM holds operands in m16n8k8 frag order.
// minBlocksPerMP=2 clamps regs to 128 -> 2 CTA/SM residency (R4: occ=11.8%@1CTA)
// ---------------------------------------------------------------------------
__global__ __launch_bounds__(256, 2)
void gemm_mma(const float* __restrict__ A, const float* __restrict__ B,
              float* __restrict__ C, const float* __restrict__ bias,
              int K, int ldB, int ldC)
{
    extern __shared__ uint32_t smem[];
    constexpr int AFRAG = 128*32;         // 4096
    constexpr int BFRAG = 128*32;         // 4096

    const int tid  = threadIdx.x;
    const int lane = tid & 31, wid = tid >> 5;
    const int wm = wid >> 2, wn = wid & 3;
    const int rowbase = blockIdx.y * 128;
    const int colbase = blockIdx.x * 128;

    float acc[4][4][4];
    #pragma unroll
    for (int mi = 0; mi < 4; mi++)
        #pragma unroll
        for (int ni = 0; ni < 4; ni++)
            #pragma unroll
            for (int j = 0; j < 4; j++) acc[mi][ni][j] = 0.f;

    const int NC = K >> 5;
    float4 fa[4], fb[4];

    auto load_chunk = [&](int k0) {
        #pragma unroll
        for (int i = 0; i < 4; i++) {
            int idx = tid + (i<<8); int r = idx>>3, c4 = idx&7;
            fa[i] = *(const float4*)(A + (size_t)(rowbase+r)*K + k0 + (c4<<2));
        }
        #pragma unroll
        for (int i = 0; i < 4; i++) {
            int idx = tid + (i<<8); int kk = idx>>5, c4 = idx&31;
            fb[i] = *(const float4*)(B + (size_t)(k0+kk)*ldB + colbase + (c4<<2));
        }
    };

    load_chunk(0);

    for (int c = 0; c < NC; c++) {
        uint32_t* af = smem + (c&1)*(AFRAG+BFRAG);
        uint32_t* bf = af + AFRAG;

        #pragma unroll
        for (int i = 0; i < 4; i++) {
            int idx = tid + (i<<8); int r = idx>>3, c4 = idx&7;
            int mtile = r>>4, rr = r&15;
            int kst = c4>>1;
            uint32_t base = (uint32_t)((mtile*4 + kst)*128)
                          + ((rr&7)<<4) + ((c4&1)<<1) + (rr>>3);
            const float* pv = &fa[i].x;
            #pragma unroll
            for (int j = 0; j < 4; j++)
                af[base + (j<<2)] = f2tf32(pv[j]);
        }
        #pragma unroll
        for (int i = 0; i < 4; i++) {
            int idx = tid + (i<<8); int kk = idx>>5, c4 = idx&31;
            int kst = kk>>3, kr = kk&7;
            int ntile = c4>>1;
            uint32_t base = (uint32_t)((ntile*4 + kst)*64)
                          + ((c4&1)<<5) + ((kr&3)<<1) + (kr>>2);
            const float* pv = &fb[i].x;
            #pragma unroll
            for (int j = 0; j < 4; j++)
                bf[base + (j<<3)] = f2tf32(pv[j]);
        }

        if (c + 1 < NC) load_chunk((c+1) << 5);
        __syncthreads();

        #pragma unroll
        for (int ks = 0; ks < 4; ks++) {
            uint4 av[4]; uint2 bv[4];
            #pragma unroll
            for (int mi = 0; mi < 4; mi++)
                av[mi] = *(const uint4*)(af + (((wm*4+mi)*4 + ks)*32 + lane)*4);
            #pragma unroll
            for (int ni = 0; ni < 4; ni++)
                bv[ni] = *(const uint2*)(bf + (((wn*4+ni)*4 + ks)*32 + lane)*2);
            #pragma unroll
            for (int mi = 0; mi < 4; mi++)
                #pragma unroll
                for (int ni = 0; ni < 4; ni++)
                    mma_tf32(acc[mi][ni], (const uint32_t*)&av[mi], (const uint32_t*)&bv[ni]);
        }
    }

    const int g = lane >> 2, t = lane & 3;
    #pragma unroll
    for (int mi = 0; mi < 4; mi++) {
        int row = rowbase + (wm*4 + mi)*16 + g;
        #pragma unroll
        for (int ni = 0; ni < 4; ni++) {
            int col = colbase + (wn*4 + ni)*8 + 2*t;
            float2 b0 = make_float2(0.f, 0.f);
            if (bias) b0 = *(const float2*)(bias + col);
            float2 v0, v1;
            v0.x = acc[mi][ni][0] + b0.x;
            v0.y = acc[mi][ni][1] + b0.y;
            v1.x = acc[mi][ni][2] + b0.x;
            v1.y = acc[mi][ni][3] + b0.y;
            float* p = C + (size_t)row*ldC + col;
            *(float2*)p           = v0;
            *(float2*)(p + 8*ldC) = v1;
        }
    }
}

// ---------------------------------------------------------------------------
// Fused flash attention per (q-tile 128, head):
//   S = (Q/32) @ K^T, online softmax, O = P @ V, ctx[b,s,h*64+d] = O / l
// grid (SSEQ/128, HEADS), 256 threads (8 warps, 2x4).
// ---------------------------------------------------------------------------
__global__ __launch_bounds__(256, 1)
void flash_kernel(const float* __restrict__ Q, const float* __restrict__ K,
                  const float* __restrict__ V, float* __restrict__ ctx)
{
    extern __shared__ uint32_t smem[];
    uint32_t* Qf = smem;                  // 8x8x128   = 8192  (A-frag, KSTEPS=8)
    uint32_t* Kf = Qf + 8192;             // 16x8x64   = 8192  (B-frag, KSTEPS=8)
    uint32_t* Vf = Kf + 8192;             // 8x16x64   = 8192  (B-frag, KSTEPS=16)
    uint32_t* Pf = Vf + 8192;             // 8x16x128  = 16384 (A-frag, KSTEPS=16)
    float* rmaxp = (float*)(Pf + 16384);  // [4][128]
    float* rsump = rmaxp + 512;           // [4][128]

    const int tid = threadIdx.x, lane = tid & 31, wid = tid >> 5;
    const int wm = wid >> 2, wn = wid & 3;
    const int g = lane >> 2, t = lane & 3;
    const int z = blockIdx.y;
    const int qbase = blockIdx.x * 128;
    const float* Qh = Q + (size_t)z*HEAD_ELEMS;
    const float* Kh = K + (size_t)z*HEAD_ELEMS;
    const float* Vh = V + (size_t)z*HEAD_ELEMS;

    // Load Q tile (128x64) -> A-frag layout, pre-scaled by 1/32 (exact)
    #pragma unroll
    for (int i = 0; i < 8; i++) {
        int idx = tid + (i<<8);             // 0..2047
        int r = idx>>4, c4 = idx&15;
        float4 v4 = *(const float4*)(Qh + (size_t)(qbase+r)*DHEAD + (c4<<2));
        int mtile = r>>4, rr = r&15;
        int kst = c4>>1;
        uint32_t base = (uint32_t)((mtile*8 + kst)*128)
                      + ((rr&7)<<4) + ((c4&1)<<1) + (rr>>3);
        const float* pv = &v4.x;
        #pragma unroll
        for (int j = 0; j < 4; j++)
            Qf[base + (j<<2)] = f2tf32(pv[j] * 0.03125f);
    }

    float accO[4][2][4];
    float mrow[4][2], lrow[4][2];
    #pragma unroll
    for (int mi = 0; mi < 4; mi++) {
        #pragma unroll
        for (int ni = 0; ni < 2; ni++)
            #pragma unroll
            for (int j = 0; j < 4; j++) accO[mi][ni][j] = 0.f;
        mrow[mi][0] = mrow[mi][1] = -1e30f;
        lrow[mi][0] = lrow[mi][1] = 0.f;
    }

    for (int kv = 0; kv < 8; kv++) {
        __syncthreads();    // guard Kf/Vf against prior-iter mma reads
        const int kvb = kv * 128;

        // K tile (128 tok x 64): NK scatter, KSTEPS=8
        #pragma unroll
        for (int i = 0; i < 8; i++) {
            int idx = tid + (i<<8);
            int n = idx>>4, c4 = idx&15;
            float4 v4 = *(const float4*)(Kh + (size_t)(kvb+n)*DHEAD + (c4<<2));
            int ntile = n>>3, gg = n&7;
            int kst = c4>>1;
            uint32_t base = (uint32_t)((ntile*8 + kst)*64) + (gg<<3) + (c4&1);
            const float* pv = &v4.x;
            #pragma unroll
            for (int j = 0; j < 4; j++)
                Kf[base + (j<<1)] = f2tf32(pv[j]);
        }
        // V tile (128 tok x 64): KN scatter (k=token, n=d), KSTEPS=16
        #pragma unroll
        for (int i = 0; i < 8; i++) {
            int idx = tid + (i<<8);
            int kk = idx>>4, c4 = idx&15;
            float4 v4 = *(const float4*)(Vh + (size_t)(kvb+kk)*DHEAD + (c4<<2));
            int kst = kk>>3, kr = kk&7;
            int ntile = c4>>1;
            uint32_t base = (uint32_t)((ntile*16 + kst)*64)
                          + ((c4&1)<<5) + ((kr&3)<<1) + (kr>>2);
            const float* pv = &v4.x;
            #pragma unroll
            for (int j = 0; j < 4; j++)
                Vf[base + (j<<3)] = f2tf32(pv[j]);
        }
        __syncthreads();    // K/V (and Q on iter 0) visible

        // ---- S = Qs @ K^T : warp tile 64x32 ----
        float accS[4][4][4];
        #pragma unroll
        for (int mi = 0; mi < 4; mi++)
            #pragma unroll
            for (int ni = 0; ni < 4; ni++)
                #pragma unroll
                for (int j = 0; j < 4; j++) accS[mi][ni][j] = 0.f;
        #pragma unroll
        for (int ks = 0; ks < 8; ks++) {
            uint4 av[4]; uint2 bv[4];
            #pragma unroll
            for (int mi = 0; mi < 4; mi++)
                av[mi] = *(const uint4*)(Qf + (((wm*4+mi)*8 + ks)*128 + lane*4));
            #pragma unroll
            for (int ni = 0; ni < 4; ni++)
                bv[ni] = *(const uint2*)(Kf + (((wn*4+ni)*8 + ks)*64 + lane*2));
            #pragma unroll
            for (int mi = 0; mi < 4; mi++)
                #pragma unroll
                for (int ni = 0; ni < 4; ni++)
                    mma_tf32(accS[mi][ni], (const uint32_t*)&av[mi], (const uint32_t*)&bv[ni]);
        }

        // ---- row max partials (per 32-col warp slice) ----
        #pragma unroll
        for (int mi = 0; mi < 4; mi++)
            #pragma unroll
            for (int h = 0; h < 2; h++) {
                float v = -1e30f;
                #pragma unroll
                for (int ni = 0; ni < 4; ni++)
                    v = fmaxf(v, fmaxf(accS[mi][ni][2*h], accS[mi][ni][2*h+1]));
                v = fmaxf(v, __shfl_xor_sync(0xffffffffu, v, 1));
                v = fmaxf(v, __shfl_xor_sync(0xffffffffu, v, 2));
                if (t == 0)
                    rmaxp[wn*128 + wm*64 + mi*16 + h*8 + g] = v;
            }
        __syncthreads();

        // ---- combine max, rescale, exp, write P (A-frag) + sum partials ----
        #pragma unroll
        for (int mi = 0; mi < 4; mi++)
            #pragma unroll
            for (int h = 0; h < 2; h++) {
                int ridx = wm*64 + mi*16 + h*8 + g;
                float tm = fmaxf(fmaxf(rmaxp[ridx], rmaxp[128+ridx]),
                                 fmaxf(rmaxp[256+ridx], rmaxp[384+ridx]));
                float mnew = fmaxf(mrow[mi][h], tm);
                float corr = __expf(mrow[mi][h] - mnew);
                mrow[mi][h] = mnew;
                lrow[mi][h] *= corr;
                #pragma unroll
                for (int ni = 0; ni < 2; ni++) {
                    accO[mi][ni][2*h]   *= corr;
                    accO[mi][ni][2*h+1] *= corr;
                }
                float s = 0.f;
                #pragma unroll
                for (int ni = 0; ni < 4; ni++) {
                    float p0 = __expf(accS[mi][ni][2*h]   - mnew);
                    float p1 = __expf(accS[mi][ni][2*h+1] - mnew);
                    s += p0 + p1;
                    uint32_t base = (uint32_t)(((wm*4+mi)*16 + wn*4 + ni)*128)
                                  + (g<<4) + ((t&1)<<3) + ((t>=2)?2:0) + h;
                    Pf[base]     = f2tf32(p0);
                    Pf[base + 4] = f2tf32(p1);
                }
                s += __shfl_xor_sync(0xffffffffu, s, 1);
                s += __shfl_xor_sync(0xffffffffu, s, 2);
                if (t == 0)
                    rsump[wn*128 + ridx] = s;
            }
        __syncthreads();

        // ---- accumulate l; O += P @ V : warp tile 64x16 ----
        #pragma unroll
        for (int mi = 0; mi < 4; mi++)
            #pragma unroll
            for (int h = 0; h < 2; h++) {
                int ridx = wm*64 + mi*16 + h*8 + g;
                lrow[mi][h] += rsump[ridx] + rsump[128+ridx]
                             + rsump[256+ridx] + rsump[384+ridx];
            }
        #pragma unroll
        for (int ks = 0; ks < 16; ks++) {
            uint4 av[4]; uint2 bv[2];
            #pragma unroll
            for (int mi = 0; mi < 4; mi++)
                av[mi] = *(const uint4*)(Pf + (((wm*4+mi)*16 + ks)*128 + lane*4));
            #pragma unroll
            for (int ni = 0; ni < 2; ni++)
                bv[ni] = *(const uint2*)(Vf + (((wn*2+ni)*16 + ks)*64 + lane*2));
            #pragma unroll
            for (int mi = 0; mi < 4; mi++)
                #pragma unroll
                for (int ni = 0; ni < 2; ni++)
                    mma_tf32(accO[mi][ni], (const uint32_t*)&av[mi], (const uint32_t*)&bv[ni]);
        }
    }

    // ---- epilogue: O / l -> ctx[b, qbase+row, h*64 + col] ----
    const int bidx = z >> 4, hidx = z & 15;
    #pragma unroll
    for (int mi = 0; mi < 4; mi++)
        #pragma unroll
        for (int h = 0; h < 2; h++) {
            float inv = 1.0f / lrow[mi][h];
            int row = qbase + wm*64 + mi*16 + h*8 + g;
            float* base = ctx + ((size_t)bidx*SSEQ + row)*EEMB + hidx*DHEAD;
            #pragma unroll
            for (int ni = 0; ni < 2; ni++) {
                int col = wn*16 + ni*8 + 2*t;
                float2 v;
                v.x = accO[mi][ni][2*h]   * inv;
                v.y = accO[mi][ni][2*h+1] * inv;
                *(float2*)(base + col) = v;
            }
        }
}

// ---------------------------------------------------------------------------
// Launch
// ---------------------------------------------------------------------------
extern "C" void kernel_launch(void* const* d_in, const int* in_sizes, int n_in,
                              void* d_out, int out_size)
{
    const float* hs = (const float*)d_in[0];
    const float* wq = (const float*)d_in[1];
    const float* wk = (const float*)d_in[2];
    const float* wv = (const float*)d_in[3];
    const float* wo = (const float*)d_in[4];
    const float* bo = (const float*)d_in[5];
    float* out = (float*)d_out;

    float *q, *k, *v, *ctx;
    cudaGetSymbolAddress((void**)&q,   g_q);
    cudaGetSymbolAddress((void**)&k,   g_k);
    cudaGetSymbolAddress((void**)&v,   g_v);
    cudaGetSymbolAddress((void**)&ctx, g_ctx);

    const int SMG = 2*(128*32 + 128*32)*4;                    // 65536
    const int SMF = (8192*3 + 16384)*4 + 2*512*4;             // 167936
    cudaFuncSetAttribute(gemm_mma,     cudaFuncAttributeMaxDynamicSharedMemorySize, SMG);
    cudaFuncSetAttribute(flash_kernel, cudaFuncAttributeMaxDynamicSharedMemorySize, SMF);

    // Q/K/V projections
    dim3 gProj(EEMB/128, MTOT/128);             // (8, 64)
    gemm_mma<<<gProj, 256, SMG>>>(hs, wq, q, nullptr, EEMB, EEMB, EEMB);
    gemm_mma<<<gProj, 256, SMG>>>(hs, wk, k, nullptr, EEMB, EEMB, EEMB);
    gemm_mma<<<gProj, 256, SMG>>>(hs, wv, v, nullptr, EEMB, EEMB, EEMB);

    // Fused attention
    dim3 gF(SSEQ/128, HEADS);                   // (8, 128)
    flash_kernel<<<gF, 256, SMF>>>(q, k, v, ctx);

    // Output projection + bias
    gemm_mma<<<gProj, 256, SMG>>>(ctx, wo, out, bo, EEMB, EEMB, EEMB);
}